// round 6
// baseline (speedup 1.0000x reference)
#include <cuda_runtime.h>
#include <cstdint>

// MazeBrain: recurrent adaptive-LIF, T=1200, B=16, N=1024.
// One CTA per batch. 256 threads x 4 cols (float4 gather, 16 loads in flight).
// Dual-parity monotonic spike rings, warp-aggregated ballot append,
// ONE barrier per step.

#define T_STEPS 1200
#define BATCH   16
#define NN      1024
#define WHIST   1000
#define TPB     256     // thread owns neurons 4*tid .. 4*tid+3

__global__ void __launch_bounds__(TPB, 1)
mazebrain_kernel(const float* __restrict__ Iext,   // [T,B,N]
                 const float* __restrict__ W,      // [N,N]
                 float* __restrict__ out)          // [2,T,B,N]: spikes, potentials
{
    const int b    = blockIdx.x;
    const int tid  = threadIdx.x;
    const int lane = tid & 31;
    const int m0   = tid * 4;

    __shared__ int s_list[2][NN];   // per-parity spike ring
    __shared__ int s_cnt[2];        // per-parity monotonic counters

    if (tid == 0) { s_cnt[0] = 0; s_cnt[1] = 0; }
    __syncthreads();

    float v[4], adapt[4], thr[4], rsum[4];
    int   refr[4];
#pragma unroll
    for (int k = 0; k < 4; k++) {
        v[k] = -65.0f; adapt[k] = 0.0f; thr[k] = -55.0f; rsum[k] = 0.0f; refr[k] = 0;
    }
    int consumed[2] = {0, 0};

    float* __restrict__ spikes_out = out;
    float* __restrict__ pot_out    = out + (size_t)T_STEPS * BATCH * NN;
    const size_t stride = (size_t)BATCH * NN;
    const float* __restrict__ Wm = W + m0;

    size_t ob = (size_t)b * NN + m0;
    float4 Ie_next   = __ldg((const float4*)(Iext + ob));
    float4 hist_next = make_float4(0.f, 0.f, 0.f, 0.f);

    for (int t = 0; t < T_STEPS; t++) {
        const int p = t & 1;        // append parity
        const int q = p ^ 1;        // consume parity
        const float4 Ie   = Ie_next;
        const float4 hist = hist_next;

        // ---- sparse gather of previous step's spikes
        const int e = s_cnt[q];
        int i = consumed[q];
        int n = e - i;
        consumed[q] = e;
        const int* __restrict__ lst = s_list[q];

        float a0 = Ie.x, a1 = Ie.y, a2 = Ie.z, a3 = Ie.w;
        while (n >= 16) {
            int j[16];
#pragma unroll
            for (int k = 0; k < 16; k++) j[k] = lst[(i + k) & (NN - 1)];
            float4 r[16];
#pragma unroll
            for (int k = 0; k < 16; k++)
                r[k] = *(const float4*)(Wm + ((size_t)j[k] << 10));
#pragma unroll
            for (int k = 0; k < 16; k++) {
                a0 += r[k].x; a1 += r[k].y; a2 += r[k].z; a3 += r[k].w;
            }
            i += 16; n -= 16;
        }
        if (n >= 8) {
            int j[8];
#pragma unroll
            for (int k = 0; k < 8; k++) j[k] = lst[(i + k) & (NN - 1)];
            float4 r[8];
#pragma unroll
            for (int k = 0; k < 8; k++)
                r[k] = *(const float4*)(Wm + ((size_t)j[k] << 10));
#pragma unroll
            for (int k = 0; k < 8; k++) {
                a0 += r[k].x; a1 += r[k].y; a2 += r[k].z; a3 += r[k].w;
            }
            i += 8; n -= 8;
        }
        if (n >= 4) {
            int j[4];
#pragma unroll
            for (int k = 0; k < 4; k++) j[k] = lst[(i + k) & (NN - 1)];
            float4 r[4];
#pragma unroll
            for (int k = 0; k < 4; k++)
                r[k] = *(const float4*)(Wm + ((size_t)j[k] << 10));
#pragma unroll
            for (int k = 0; k < 4; k++) {
                a0 += r[k].x; a1 += r[k].y; a2 += r[k].z; a3 += r[k].w;
            }
            i += 4; n -= 4;
        }
        while (n > 0) {
            float4 r = *(const float4*)(Wm + ((size_t)lst[i & (NN - 1)] << 10));
            a0 += r.x; a1 += r.y; a2 += r.z; a3 += r.w;
            i++; n--;
        }
        float Iin[4] = {a0, a1, a2, a3};

        // ---- neuron update (integrate -> fire/reset -> adapt -> homeo)
        float spk[4], vout[4];
        bool  fired[4];
#pragma unroll
        for (int k = 0; k < 4; k++) {
            bool  active = (refr[k] <= 0);
            float v_int  = 0.9f * (v[k] + 65.0f) - 65.0f + Iin[k] - adapt[k];
            float v1     = active ? v_int : v[k];
            int   r1     = active ? refr[k] : (refr[k] - 1);
            fired[k] = (v1 >= thr[k]);
            spk[k]  = fired[k] ? 1.0f : 0.0f;
            v[k]    = fired[k] ? -70.0f : v1;
            vout[k] = v[k];
            adapt[k] = (fired[k] ? (adapt[k] + 0.2f) : adapt[k]) * 0.95f;
            refr[k]  = fired[k] ? 5 : r1;
        }

        // ---- warp-aggregated append: 4 ballots, 1 atomic per warp, STS offsets
        uint32_t b0 = __ballot_sync(0xffffffffu, fired[0]);
        uint32_t b1 = __ballot_sync(0xffffffffu, fired[1]);
        uint32_t b2 = __ballot_sync(0xffffffffu, fired[2]);
        uint32_t b3 = __ballot_sync(0xffffffffu, fired[3]);
        const int c0 = __popc(b0), c1 = __popc(b1), c2 = __popc(b2), c3 = __popc(b3);
        const int wtot = c0 + c1 + c2 + c3;
        if (wtot) {
            int base = 0;
            if (lane == 0) base = atomicAdd(&s_cnt[p], wtot);
            base = __shfl_sync(0xffffffffu, base, 0);
            const uint32_t lt = (1u << lane) - 1u;
            if (fired[0]) s_list[p][(base + __popc(b0 & lt)) & (NN - 1)] = m0;
            if (fired[1]) s_list[p][(base + c0 + __popc(b1 & lt)) & (NN - 1)] = m0 + 1;
            if (fired[2]) s_list[p][(base + c0 + c1 + __popc(b2 & lt)) & (NN - 1)] = m0 + 2;
            if (fired[3]) s_list[p][(base + c0 + c1 + c2 + __popc(b3 & lt)) & (NN - 1)] = m0 + 3;
        }

        // ---- outputs (spikes region doubles as the homeostatic history ring)
        *(float4*)(spikes_out + ob) = make_float4(spk[0], spk[1], spk[2], spk[3]);
        *(float4*)(pot_out    + ob) = make_float4(vout[0], vout[1], vout[2], vout[3]);

        // ---- homeostatic sliding-window rate
        rsum[0] += spk[0] - hist.x; rsum[1] += spk[1] - hist.y;
        rsum[2] += spk[2] - hist.z; rsum[3] += spk[3] - hist.w;
        if (t + 1 >= WHIST) {
#pragma unroll
            for (int k = 0; k < 4; k++) {
                float ta = thr[k] + 0.001f * (rsum[k] * (1.0f / WHIST) - 0.01f);
                thr[k] = fminf(fmaxf(ta, 0.1f), 5.0f);
            }
        }

        // ---- prefetch next step's inputs
        const size_t ob_next = ob + stride;
        if (t + 1 < T_STEPS) {
            Ie_next = __ldg((const float4*)(Iext + ob_next));
            hist_next = (t + 1 >= WHIST)
                      ? *(const float4*)(spikes_out + (ob_next - (size_t)WHIST * stride))
                      : make_float4(0.f, 0.f, 0.f, 0.f);
        }
        ob = ob_next;

        __syncthreads();   // orders append(t) before gather(t+1)
    }
}

extern "C" void kernel_launch(void* const* d_in, const int* in_sizes, int n_in,
                              void* d_out, int out_size)
{
    const float* input_current = (const float*)d_in[0];  // [T,B,N]
    const float* W_rec         = (const float*)d_in[1];  // [N,N]
    float* out                 = (float*)d_out;          // [2,T,B,N]
    (void)in_sizes; (void)n_in; (void)out_size;

    mazebrain_kernel<<<BATCH, TPB>>>(input_current, W_rec, out);
}